// round 2
// baseline (speedup 1.0000x reference)
#include <cuda_runtime.h>
#include <cuda_bf16.h>
#include <math.h>

// Problem constants
#define BB 32
#define EE 512
#define HH 1024
#define VV 32000
#define TT 64
#define START_TOK 1
#define F32_TINY 1.17549435e-38f

// ---------------- device scratch (no cudaMalloc allowed) ----------------
__device__ float g_hA[HH * BB];   // h transposed: h[b][k] at [k*32 + b]
__device__ float g_hB[HH * BB];
__device__ float g_cA[HH * BB];
__device__ float g_cB[HH * BB];
__device__ int   g_tok[BB];
__device__ unsigned long long g_part[BB * 256]; // per-(b, block) packed argmax

// ---------------- f32x2 packed math ----------------
__device__ __forceinline__ unsigned long long pack2(float lo, float hi) {
    unsigned long long r;
    asm("mov.b64 %0, {%1, %2};" : "=l"(r) : "f"(lo), "f"(hi));
    return r;
}
__device__ __forceinline__ void unpack2(unsigned long long v, float& lo, float& hi) {
    asm("mov.b64 {%0, %1}, %2;" : "=f"(lo), "=f"(hi) : "l"(v));
}
__device__ __forceinline__ unsigned long long fma2(unsigned long long a,
                                                   unsigned long long b,
                                                   unsigned long long c) {
    unsigned long long d;
    asm("fma.rn.f32x2 %0, %1, %2, %3;" : "=l"(d) : "l"(a), "l"(b), "l"(c));
    return d;
}

// ---------------- threefry2x32 (JAX-compatible, 20 rounds) ----------------
__device__ __forceinline__ void threefry2x32_dev(unsigned k0, unsigned k1,
                                                 unsigned x0, unsigned x1,
                                                 unsigned& o0, unsigned& o1) {
    unsigned ks2 = k0 ^ k1 ^ 0x1BD11BDAu;
    x0 += k0; x1 += k1;
#define TF_RND(r) { x0 += x1; x1 = __funnelshift_l(x1, x1, r); x1 ^= x0; }
    TF_RND(13) TF_RND(15) TF_RND(26) TF_RND(6)  x0 += k1;  x1 += ks2 + 1u;
    TF_RND(17) TF_RND(29) TF_RND(16) TF_RND(24) x0 += ks2; x1 += k0 + 2u;
    TF_RND(13) TF_RND(15) TF_RND(26) TF_RND(6)  x0 += k0;  x1 += k1 + 3u;
    TF_RND(17) TF_RND(29) TF_RND(16) TF_RND(24) x0 += k1;  x1 += ks2 + 4u;
    TF_RND(13) TF_RND(15) TF_RND(26) TF_RND(6)  x0 += ks2; x1 += k0 + 5u;
#undef TF_RND
    o0 = x0; o1 = x1;
}

// monotone float -> uint32 map for packed argmax keys
__device__ __forceinline__ unsigned ford(float f) {
    unsigned u = __float_as_uint(f);
    return (u & 0x80000000u) ? ~u : (u | 0x80000000u);
}
__device__ __forceinline__ unsigned long long u64max(unsigned long long a,
                                                     unsigned long long b) {
    return a > b ? a : b;
}

// ---------------- K0: h0/c0 from condition; tok = START ----------------
// 1024 warps (one per j). lane = b.
__global__ __launch_bounds__(256) void init_kernel(
    const float* __restrict__ cond, const float* __restrict__ Wh,
    const float* __restrict__ bh,   const float* __restrict__ Wc,
    const float* __restrict__ bc,
    float* __restrict__ hout, float* __restrict__ cout, int* __restrict__ tok) {
    int j = blockIdx.x * 8 + (threadIdx.x >> 5);
    int lane = threadIdx.x & 31;
    const float* cr = cond + (size_t)lane * EE;
    const float* wh = Wh + (size_t)j * EE;
    const float* wc = Wc + (size_t)j * EE;
    float ah = bh[j], ac = bc[j];
#pragma unroll 4
    for (int k = 0; k < EE; k += 4) {
        float4 c4 = *(const float4*)(cr + k);
        float4 h4 = *(const float4*)(wh + k);
        float4 q4 = *(const float4*)(wc + k);
        ah = fmaf(c4.x, h4.x, ah); ah = fmaf(c4.y, h4.y, ah);
        ah = fmaf(c4.z, h4.z, ah); ah = fmaf(c4.w, h4.w, ah);
        ac = fmaf(c4.x, q4.x, ac); ac = fmaf(c4.y, q4.y, ac);
        ac = fmaf(c4.z, q4.z, ac); ac = fmaf(c4.w, q4.w, ac);
    }
    hout[j * BB + lane] = ah;
    cout[j * BB + lane] = ac;
    if (blockIdx.x == 0 && threadIdx.x < BB) tok[threadIdx.x] = START_TOK;
}

// ---------------- K1: one LSTM cell step ----------------
// 1024 warps (one per hidden unit j), lane = b. Computes 4 gate dots.
__global__ __launch_bounds__(256) void lstm_kernel(
    const int* __restrict__ tok, const float* __restrict__ embed,
    const float* __restrict__ Wih, const float* __restrict__ bih,
    const float* __restrict__ Whh, const float* __restrict__ bhh,
    const float* __restrict__ hin, const float* __restrict__ cin,
    float* __restrict__ hout, float* __restrict__ cout) {
    int j = blockIdx.x * 8 + (threadIdx.x >> 5);
    int lane = threadIdx.x & 31;
    const float* xr = embed + (size_t)tok[lane] * EE;
    float a0 = bih[j]        + bhh[j];
    float a1 = bih[j + 1024] + bhh[j + 1024];
    float a2 = bih[j + 2048] + bhh[j + 2048];
    float a3 = bih[j + 3072] + bhh[j + 3072];
    {
        const float* w0 = Wih + (size_t)j * EE;
        const float* w1 = Wih + (size_t)(j + 1024) * EE;
        const float* w2 = Wih + (size_t)(j + 2048) * EE;
        const float* w3 = Wih + (size_t)(j + 3072) * EE;
#pragma unroll 2
        for (int k = 0; k < EE; k += 4) {
            float4 x4 = *(const float4*)(xr + k);
            float4 p0 = *(const float4*)(w0 + k);
            float4 p1 = *(const float4*)(w1 + k);
            float4 p2 = *(const float4*)(w2 + k);
            float4 p3 = *(const float4*)(w3 + k);
            a0 = fmaf(x4.x, p0.x, a0); a0 = fmaf(x4.y, p0.y, a0);
            a0 = fmaf(x4.z, p0.z, a0); a0 = fmaf(x4.w, p0.w, a0);
            a1 = fmaf(x4.x, p1.x, a1); a1 = fmaf(x4.y, p1.y, a1);
            a1 = fmaf(x4.z, p1.z, a1); a1 = fmaf(x4.w, p1.w, a1);
            a2 = fmaf(x4.x, p2.x, a2); a2 = fmaf(x4.y, p2.y, a2);
            a2 = fmaf(x4.z, p2.z, a2); a2 = fmaf(x4.w, p2.w, a2);
            a3 = fmaf(x4.x, p3.x, a3); a3 = fmaf(x4.y, p3.y, a3);
            a3 = fmaf(x4.z, p3.z, a3); a3 = fmaf(x4.w, p3.w, a3);
        }
    }
    {
        const float* u0 = Whh + (size_t)j * HH;
        const float* u1 = Whh + (size_t)(j + 1024) * HH;
        const float* u2 = Whh + (size_t)(j + 2048) * HH;
        const float* u3 = Whh + (size_t)(j + 3072) * HH;
#pragma unroll 2
        for (int k = 0; k < HH; k += 4) {
            float h0 = hin[(k + 0) * BB + lane];
            float h1 = hin[(k + 1) * BB + lane];
            float h2 = hin[(k + 2) * BB + lane];
            float h3 = hin[(k + 3) * BB + lane];
            float4 q0 = *(const float4*)(u0 + k);
            float4 q1 = *(const float4*)(u1 + k);
            float4 q2 = *(const float4*)(u2 + k);
            float4 q3 = *(const float4*)(u3 + k);
            a0 = fmaf(h0, q0.x, a0); a0 = fmaf(h1, q0.y, a0);
            a0 = fmaf(h2, q0.z, a0); a0 = fmaf(h3, q0.w, a0);
            a1 = fmaf(h0, q1.x, a1); a1 = fmaf(h1, q1.y, a1);
            a1 = fmaf(h2, q1.z, a1); a1 = fmaf(h3, q1.w, a1);
            a2 = fmaf(h0, q2.x, a2); a2 = fmaf(h1, q2.y, a2);
            a2 = fmaf(h2, q2.z, a2); a2 = fmaf(h3, q2.w, a2);
            a3 = fmaf(h0, q3.x, a3); a3 = fmaf(h1, q3.y, a3);
            a3 = fmaf(h2, q3.z, a3); a3 = fmaf(h3, q3.w, a3);
        }
    }
    float ig = 1.0f / (1.0f + expf(-a0));
    float fg = 1.0f / (1.0f + expf(-a1));
    float gg = tanhf(a2);
    float og = 1.0f / (1.0f + expf(-a3));
    float c  = fg * cin[j * BB + lane] + ig * gg;
    float h  = og * tanhf(c);
    cout[j * BB + lane] = c;
    hout[j * BB + lane] = h;
}

// ---------------- K2: logits GEMM + gumbel + per-block argmax ----------------
// Block: 256 threads = 32 (vt) x 8 (bt). TILE_V = 128 (v = v0 + vt + 32*j).
// Each thread: 4 v x 4 b accumulators as f32x2 pairs.
__global__ __launch_bounds__(256) void logits_kernel(
    const float* __restrict__ hT, const float* __restrict__ Wout,
    const float* __restrict__ bout, float* __restrict__ logits_out,
    unsigned long long* __restrict__ part, int t, unsigned key0, unsigned key1) {
    __shared__ float Ws[32][129];  // [k][v], pad 129 -> conflict-free
    __shared__ float hs[32][32];   // [k][b]
    int tid = threadIdx.x;
    int vt = tid & 31;
    int bt = tid >> 5;
    int v0 = blockIdx.x * 128;

    unsigned long long acc[4][2];
#pragma unroll
    for (int j = 0; j < 4; j++) { acc[j][0] = 0ull; acc[j][1] = 0ull; }

    for (int kc = 0; kc < HH; kc += 32) {
        __syncthreads();
        // stage W tile: 128 rows x 32 k, transposed into Ws[k][v]
#pragma unroll
        for (int p = 0; p < 4; p++) {
            int idx = tid + p * 256;
            int row = idx >> 3;           // v-local 0..127
            int c4  = (idx & 7) * 4;      // k-local 0..28
            float4 w4 = *(const float4*)(Wout + (size_t)(v0 + row) * HH + kc + c4);
            Ws[c4 + 0][row] = w4.x;
            Ws[c4 + 1][row] = w4.y;
            Ws[c4 + 2][row] = w4.z;
            Ws[c4 + 3][row] = w4.w;
        }
        // stage h tile: 32 k x 32 b
        {
            int k  = tid >> 3;
            int b4 = (tid & 7) * 4;
            *(float4*)&hs[k][b4] = *(const float4*)(hT + (size_t)(kc + k) * BB + b4);
        }
        __syncthreads();
#pragma unroll
        for (int k = 0; k < 32; k++) {
            float4 h4 = *(const float4*)&hs[k][bt * 4];
            unsigned long long h01 = pack2(h4.x, h4.y);
            unsigned long long h23 = pack2(h4.z, h4.w);
#pragma unroll
            for (int j = 0; j < 4; j++) {
                float w = Ws[k][vt + 32 * j];
                unsigned long long ww = pack2(w, w);
                acc[j][0] = fma2(ww, h01, acc[j][0]);
                acc[j][1] = fma2(ww, h23, acc[j][1]);
            }
        }
    }

    // epilogue: bias, store logits, gumbel, per-b argmax
    int base_b = bt * 4;
    unsigned long long bestkey[4] = {0ull, 0ull, 0ull, 0ull};
#pragma unroll
    for (int j = 0; j < 4; j++) {
        int v = v0 + vt + 32 * j;
        float bo = bout[v];
        float lg[4];
        unpack2(acc[j][0], lg[0], lg[1]);
        unpack2(acc[j][1], lg[2], lg[3]);
#pragma unroll
        for (int bi = 0; bi < 4; bi++) {
            int b = base_b + bi;
            float logit = lg[bi] + bo;
            if (logits_out)
                logits_out[(size_t)b * VV * TT + (size_t)v * TT + t] = logit;
            // JAX threefry-partitionable bits for flat index i = b*V + v
            unsigned i = (unsigned)(b * VV + v);
            unsigned o0, o1;
            threefry2x32_dev(key0, key1, 0u, i, o0, o1);
            unsigned bits = o0 ^ o1;
            float u = __uint_as_float(0x3f800000u | (bits >> 9)) - 1.0f;
            u = fmaxf(u + F32_TINY, F32_TINY);
            float g = -logf(-logf(u));
            float val = logit + g;
            unsigned long long key =
                ((unsigned long long)ford(val) << 32) |
                (unsigned long long)(0xFFFFFFFFu - (unsigned)v);
            bestkey[bi] = u64max(bestkey[bi], key);
        }
    }
#pragma unroll
    for (int off = 16; off; off >>= 1) {
#pragma unroll
        for (int bi = 0; bi < 4; bi++) {
            unsigned long long o = __shfl_xor_sync(0xffffffffu, bestkey[bi], off);
            bestkey[bi] = u64max(bestkey[bi], o);
        }
    }
    if (vt == 0) {
#pragma unroll
        for (int bi = 0; bi < 4; bi++)
            part[(base_b + bi) * 256 + blockIdx.x] = bestkey[bi];
    }
}

// ---------------- K3: final argmax over block partials -> token ----------------
__global__ void sample_kernel(const unsigned long long* __restrict__ part,
                              int nblocks, int* __restrict__ tok,
                              float* __restrict__ cap_f, int* __restrict__ cap_i,
                              int t) {
    int b = threadIdx.x >> 5;
    int lane = threadIdx.x & 31;
    unsigned long long best = 0ull;
    for (int idx = lane; idx < nblocks; idx += 32)
        best = u64max(best, part[b * 256 + idx]);
#pragma unroll
    for (int off = 16; off; off >>= 1)
        best = u64max(best, __shfl_xor_sync(0xffffffffu, best, off));
    if (lane == 0) {
        int v = (int)(0xFFFFFFFFu - (unsigned)(best & 0xFFFFFFFFull));
        tok[b] = v;
        if (cap_f) cap_f[b * TT + t] = (float)v;
        if (cap_i) cap_i[b * TT + t] = v;
    }
}

// ---------------- host threefry (per-step fold_in keys, baked into graph) ----
static void host_threefry(unsigned k0, unsigned k1, unsigned x0, unsigned x1,
                          unsigned& o0, unsigned& o1) {
    unsigned ks2 = k0 ^ k1 ^ 0x1BD11BDAu;
    x0 += k0; x1 += k1;
#define HTF_RND(r) { x0 += x1; x1 = (x1 << r) | (x1 >> (32 - r)); x1 ^= x0; }
    HTF_RND(13) HTF_RND(15) HTF_RND(26) HTF_RND(6)  x0 += k1;  x1 += ks2 + 1u;
    HTF_RND(17) HTF_RND(29) HTF_RND(16) HTF_RND(24) x0 += ks2; x1 += k0 + 2u;
    HTF_RND(13) HTF_RND(15) HTF_RND(26) HTF_RND(6)  x0 += k0;  x1 += k1 + 3u;
    HTF_RND(17) HTF_RND(29) HTF_RND(16) HTF_RND(24) x0 += k1;  x1 += ks2 + 4u;
    HTF_RND(13) HTF_RND(15) HTF_RND(26) HTF_RND(6)  x0 += ks2; x1 += k0 + 5u;
#undef HTF_RND
    o0 = x0; o1 = x1;
}

extern "C" void kernel_launch(void* const* d_in, const int* in_sizes, int n_in,
                              void* d_out, int out_size) {
    const float* condition = (const float*)d_in[0];
    const float* Wh    = (const float*)d_in[1];
    const float* bh    = (const float*)d_in[2];
    const float* Wc    = (const float*)d_in[3];
    const float* bc    = (const float*)d_in[4];
    const float* embed = (const float*)d_in[5];
    const float* Wih   = (const float*)d_in[6];
    const float* bih   = (const float*)d_in[7];
    const float* Whh   = (const float*)d_in[8];
    const float* bhh   = (const float*)d_in[9];
    const float* Wout  = (const float*)d_in[10];
    const float* bout  = (const float*)d_in[11];

    float *hA, *hB, *cA, *cB;
    int* tokp;
    unsigned long long* part;
    cudaGetSymbolAddress((void**)&hA, g_hA);
    cudaGetSymbolAddress((void**)&hB, g_hB);
    cudaGetSymbolAddress((void**)&cA, g_cA);
    cudaGetSymbolAddress((void**)&cB, g_cB);
    cudaGetSymbolAddress((void**)&tokp, g_tok);
    cudaGetSymbolAddress((void**)&part, g_part);

    // Output routing: reference returns (captions[B,T] int32, logits[B,V,T] f32).
    const long long n_cap = (long long)BB * TT;             // 2048
    const long long n_log = (long long)BB * VV * TT;        // 65,536,000
    float* cap_f = nullptr;
    int*   cap_i = nullptr;
    float* log_out = nullptr;
    long long osz = (long long)out_size;
    if (osz == n_cap + n_log) {
        cap_f = (float*)d_out;
        log_out = (float*)d_out + n_cap;
    } else if (osz == n_log) {
        log_out = (float*)d_out;
    } else if (osz == n_cap) {
        cap_i = (int*)d_out;
    } else {
        // fallback: assume concatenated (captions, logits)
        cap_f = (float*)d_out;
        log_out = (float*)d_out + n_cap;
    }

    init_kernel<<<128, 256>>>(condition, Wh, bh, Wc, bc, hA, cA, tokp);

    float *hcur = hA, *hnxt = hB, *ccur = cA, *cnxt = cB;
    for (int t = 0; t < TT; t++) {
        lstm_kernel<<<128, 256>>>(tokp, embed, Wih, bih, Whh, bhh,
                                  hcur, ccur, hnxt, cnxt);
        // key_t = threefry_fold_in(key(42), t) = threefry2x32((0,42),(0,t))
        unsigned o0, o1;
        host_threefry(0u, 42u, 0u, (unsigned)t, o0, o1);
        logits_kernel<<<250, 256>>>(hnxt, Wout, bout, log_out, part, t, o0, o1);
        sample_kernel<<<1, 1024>>>(part, 250, tokp, cap_f, cap_i, t);
        float* tmp;
        tmp = hcur; hcur = hnxt; hnxt = tmp;
        tmp = ccur; ccur = cnxt; cnxt = tmp;
    }
}

// round 3
// speedup vs baseline: 1.7653x; 1.7653x over previous
#include <cuda_runtime.h>
#include <math.h>

#define BB 32
#define EE 512
#define HH 1024
#define VV 32000
#define TT 64
#define START_TOK 1
#define F32_TINY 1.17549435e-38f
#define KC 32
#define TILEV 128
#define NCHUNK (HH / KC)

// ---------------- device scratch ----------------
__device__ float g_hA[HH * BB];   // [k][b]
__device__ float g_hB[HH * BB];
__device__ float g_cA[HH * BB];
__device__ float g_cB[HH * BB];
__device__ float g_x[EE * BB];    // [k][b] gathered embedding
__device__ unsigned long long g_best[TT * BB];      // packed argmax keys
__device__ float g_stage[(size_t)BB * TT * VV];     // [b][t][v] staging

// ---------------- f32x2 packed math ----------------
__device__ __forceinline__ unsigned long long pack2(float lo, float hi) {
    unsigned long long r;
    asm("mov.b64 %0, {%1, %2};" : "=l"(r) : "f"(lo), "f"(hi));
    return r;
}
__device__ __forceinline__ void unpack2(unsigned long long v, float& lo, float& hi) {
    asm("mov.b64 {%0, %1}, %2;" : "=f"(lo), "=f"(hi) : "l"(v));
}
__device__ __forceinline__ unsigned long long fma2(unsigned long long a,
                                                   unsigned long long b,
                                                   unsigned long long c) {
    unsigned long long d;
    asm("fma.rn.f32x2 %0, %1, %2, %3;" : "=l"(d) : "l"(a), "l"(b), "l"(c));
    return d;
}

// ---------------- threefry2x32 (JAX-compatible) ----------------
__device__ __forceinline__ void threefry2x32_dev(unsigned k0, unsigned k1,
                                                 unsigned x0, unsigned x1,
                                                 unsigned& o0, unsigned& o1) {
    unsigned ks2 = k0 ^ k1 ^ 0x1BD11BDAu;
    x0 += k0; x1 += k1;
#define TF_RND(r) { x0 += x1; x1 = __funnelshift_l(x1, x1, r); x1 ^= x0; }
    TF_RND(13) TF_RND(15) TF_RND(26) TF_RND(6)  x0 += k1;  x1 += ks2 + 1u;
    TF_RND(17) TF_RND(29) TF_RND(16) TF_RND(24) x0 += ks2; x1 += k0 + 2u;
    TF_RND(13) TF_RND(15) TF_RND(26) TF_RND(6)  x0 += k0;  x1 += k1 + 3u;
    TF_RND(17) TF_RND(29) TF_RND(16) TF_RND(24) x0 += k1;  x1 += ks2 + 4u;
    TF_RND(13) TF_RND(15) TF_RND(26) TF_RND(6)  x0 += ks2; x1 += k0 + 5u;
#undef TF_RND
    o0 = x0; o1 = x1;
}

__device__ __forceinline__ unsigned ford(float f) {
    unsigned u = __float_as_uint(f);
    return (u & 0x80000000u) ? ~u : (u | 0x80000000u);
}
__device__ __forceinline__ unsigned long long u64max(unsigned long long a,
                                                     unsigned long long b) {
    return a > b ? a : b;
}
__device__ __forceinline__ int decode_tok(unsigned long long key) {
    return (int)(0xFFFFFFFFu - (unsigned)(key & 0xFFFFFFFFull));
}

// ---------------- K0: h0/c0 from condition; clear g_best ----------------
__global__ __launch_bounds__(256) void init_kernel(
    const float* __restrict__ cond, const float* __restrict__ Wh,
    const float* __restrict__ bh,   const float* __restrict__ Wc,
    const float* __restrict__ bc,
    float* __restrict__ hout, float* __restrict__ cout) {
    int j = blockIdx.x * 8 + (threadIdx.x >> 5);
    int lane = threadIdx.x & 31;
    if (blockIdx.x < 8) {
        int idx = blockIdx.x * 256 + threadIdx.x;
        if (idx < TT * BB) g_best[idx] = 0ull;
    }
    const float* cr = cond + (size_t)lane * EE;
    const float* wh = Wh + (size_t)j * EE;
    const float* wc = Wc + (size_t)j * EE;
    float ah = bh[j], ac = bc[j];
#pragma unroll 4
    for (int k = 0; k < EE; k += 4) {
        float4 c4 = *(const float4*)(cr + k);
        float4 h4 = *(const float4*)(wh + k);
        float4 q4 = *(const float4*)(wc + k);
        ah = fmaf(c4.x, h4.x, ah); ah = fmaf(c4.y, h4.y, ah);
        ah = fmaf(c4.z, h4.z, ah); ah = fmaf(c4.w, h4.w, ah);
        ac = fmaf(c4.x, q4.x, ac); ac = fmaf(c4.y, q4.y, ac);
        ac = fmaf(c4.z, q4.z, ac); ac = fmaf(c4.w, q4.w, ac);
    }
    hout[j * BB + lane] = ah;
    cout[j * BB + lane] = ac;
}

// ---------------- K-gather: decode token, stage x[k][b] ----------------
__global__ __launch_bounds__(256) void gather_kernel(
    const float* __restrict__ embed, float* __restrict__ xout, int t) {
    int idx = blockIdx.x * 256 + threadIdx.x;  // 0..16383
    int b = idx & 31;
    int k = idx >> 5;
    int tok = START_TOK;
    if (t > 0) tok = decode_tok(g_best[(t - 1) * BB + b]);
    xout[k * BB + b] = embed[(size_t)tok * EE + k];
}

// ---------------- K1: gate GEMM + fused cell ----------------
// grid 512, block 256 = 8 warps. Warp w: jj = j0+(w&1), gate = w>>2? -> w>>1.
__global__ __launch_bounds__(256) void lstm_kernel(
    const float* __restrict__ x, const float* __restrict__ Wih,
    const float* __restrict__ bih, const float* __restrict__ Whh,
    const float* __restrict__ bhh, const float* __restrict__ hin,
    const float* __restrict__ cin,
    float* __restrict__ hout, float* __restrict__ cout) {
    __shared__ float gs[4][2][32];
    int tid = threadIdx.x;
    int w = tid >> 5;
    int lane = tid & 31;
    int j0 = blockIdx.x * 2;
    int jj = j0 + (w & 1);
    int gate = w >> 1;
    int r = gate * HH + jj;

    float a = bih[r] + bhh[r];
    const float* xc = x + lane;
    const float* hc = hin + lane;
    const float* wr = Wih + (size_t)r * EE;
#pragma unroll 4
    for (int k = 0; k < EE; k += 4) {
        float4 w4 = *(const float4*)(wr + k);
        a = fmaf(w4.x, xc[(k + 0) * BB], a);
        a = fmaf(w4.y, xc[(k + 1) * BB], a);
        a = fmaf(w4.z, xc[(k + 2) * BB], a);
        a = fmaf(w4.w, xc[(k + 3) * BB], a);
    }
    const float* ur = Whh + (size_t)r * HH;
#pragma unroll 4
    for (int k = 0; k < HH; k += 4) {
        float4 w4 = *(const float4*)(ur + k);
        a = fmaf(w4.x, hc[(k + 0) * BB], a);
        a = fmaf(w4.y, hc[(k + 1) * BB], a);
        a = fmaf(w4.z, hc[(k + 2) * BB], a);
        a = fmaf(w4.w, hc[(k + 3) * BB], a);
    }
    gs[gate][w & 1][lane] = a;
    __syncthreads();
    if (tid < 64) {
        int jl = tid >> 5;
        int ln = tid & 31;
        int j = j0 + jl;
        float ig = 1.0f / (1.0f + expf(-gs[0][jl][ln]));
        float fg = 1.0f / (1.0f + expf(-gs[1][jl][ln]));
        float gg = tanhf(gs[2][jl][ln]);
        float og = 1.0f / (1.0f + expf(-gs[3][jl][ln]));
        float c = fg * cin[j * BB + ln] + ig * gg;
        float h = og * tanhf(c);
        cout[j * BB + ln] = c;
        hout[j * BB + ln] = h;
    }
}

// ---------------- cp.async helpers ----------------
__device__ __forceinline__ void cp_async16(unsigned dst, const void* src) {
    asm volatile("cp.async.cg.shared.global [%0], [%1], 16;"
                 :: "r"(dst), "l"(src) : "memory");
}
__device__ __forceinline__ void cp_commit() {
    asm volatile("cp.async.commit_group;" ::: "memory");
}

// ---------------- K2: logits GEMM + gumbel + atomic argmax ----------------
// 128 threads: vt = tid&15 (v-strided), bt = tid>>4 (8 groups of 4 b).
// Thread tile: 8 v (v = v0 + vt + 16*vj) x 4 b. Double-buffered cp.async.
#define WS_STRIDE 36
__global__ __launch_bounds__(128) void logits_kernel(
    const float* __restrict__ hT, const float* __restrict__ Wout,
    const float* __restrict__ bout, float* __restrict__ stage,
    unsigned long long* __restrict__ best, int t, unsigned key0, unsigned key1) {
    __shared__ __align__(16) float Ws[2][TILEV][WS_STRIDE]; // [v][k]
    __shared__ __align__(16) float hs[2][KC][BB];           // [k][b]
    int tid = threadIdx.x;
    int vt = tid & 15;
    int bt = tid >> 4;
    int v0 = blockIdx.x * TILEV;

    // stage chunk kc into buffer buf
    auto do_stage = [&](int buf, int kc) {
        const float* wsrc = Wout + (size_t)(v0 + tid) * HH + kc;
        unsigned wdst = (unsigned)__cvta_generic_to_shared(&Ws[buf][tid][0]);
#pragma unroll
        for (int ch = 0; ch < 8; ch++)
            cp_async16(wdst + ch * 16, wsrc + ch * 4);
        const float* hsrc = hT + (size_t)kc * BB;
        unsigned hdst = (unsigned)__cvta_generic_to_shared(&hs[buf][0][0]);
#pragma unroll
        for (int c = 0; c < 2; c++) {
            int cc = tid * 2 + c;
            cp_async16(hdst + cc * 16, hsrc + cc * 4);
        }
        cp_commit();
    };

    do_stage(0, 0);

    unsigned long long acc[8][2];
#pragma unroll
    for (int vj = 0; vj < 8; vj++) { acc[vj][0] = 0ull; acc[vj][1] = 0ull; }

    for (int c = 0; c < NCHUNK; c++) {
        int buf = c & 1;
        if (c + 1 < NCHUNK) {
            do_stage(buf ^ 1, (c + 1) * KC);
            asm volatile("cp.async.wait_group 1;" ::: "memory");
        } else {
            asm volatile("cp.async.wait_group 0;" ::: "memory");
        }
        __syncthreads();
#pragma unroll
        for (int k4 = 0; k4 < KC / 4; k4++) {
            unsigned long long h01[4], h23[4];
#pragma unroll
            for (int i = 0; i < 4; i++) {
                float4 h4 = *(const float4*)&hs[buf][k4 * 4 + i][bt * 4];
                h01[i] = pack2(h4.x, h4.y);
                h23[i] = pack2(h4.z, h4.w);
            }
#pragma unroll
            for (int vj = 0; vj < 8; vj++) {
                float4 w4 = *(const float4*)&Ws[buf][vt + 16 * vj][k4 * 4];
                unsigned long long w;
                w = pack2(w4.x, w4.x);
                acc[vj][0] = fma2(w, h01[0], acc[vj][0]);
                acc[vj][1] = fma2(w, h23[0], acc[vj][1]);
                w = pack2(w4.y, w4.y);
                acc[vj][0] = fma2(w, h01[1], acc[vj][0]);
                acc[vj][1] = fma2(w, h23[1], acc[vj][1]);
                w = pack2(w4.z, w4.z);
                acc[vj][0] = fma2(w, h01[2], acc[vj][0]);
                acc[vj][1] = fma2(w, h23[2], acc[vj][1]);
                w = pack2(w4.w, w4.w);
                acc[vj][0] = fma2(w, h01[3], acc[vj][0]);
                acc[vj][1] = fma2(w, h23[3], acc[vj][1]);
            }
        }
        __syncthreads();
    }

    // epilogue: bias, store to staging [b][t][v], gumbel, argmax
    float lg[8][4];
#pragma unroll
    for (int vj = 0; vj < 8; vj++) {
        unpack2(acc[vj][0], lg[vj][0], lg[vj][1]);
        unpack2(acc[vj][1], lg[vj][2], lg[vj][3]);
        float bo = bout[v0 + vt + 16 * vj];
#pragma unroll
        for (int bi = 0; bi < 4; bi++) lg[vj][bi] += bo;
    }
#pragma unroll
    for (int bi = 0; bi < 4; bi++) {
        int b = bt * 4 + bi;
        float* sp = stage + ((size_t)b * TT + t) * VV + v0 + vt;
        unsigned long long bk = 0ull;
#pragma unroll
        for (int vj = 0; vj < 8; vj++) {
            int v = v0 + vt + 16 * vj;
            float logit = lg[vj][bi];
            sp[16 * vj] = logit;
            unsigned i = (unsigned)(b * VV + v);
            unsigned o0, o1;
            threefry2x32_dev(key0, key1, 0u, i, o0, o1);
            unsigned bits = o0 ^ o1;
            float u = __uint_as_float(0x3f800000u | (bits >> 9)) - 1.0f;
            u = fmaxf(u + F32_TINY, F32_TINY);
            float g = -logf(-logf(u));
            float val = logit + g;
            unsigned long long key =
                ((unsigned long long)ford(val) << 32) |
                (unsigned long long)(0xFFFFFFFFu - (unsigned)v);
            bk = u64max(bk, key);
        }
#pragma unroll
        for (int off = 1; off < 16; off <<= 1) {
            unsigned long long o = __shfl_xor_sync(0xffffffffu, bk, off);
            bk = u64max(bk, o);
        }
        if (vt == 0) atomicMax(&best[t * BB + b], bk);
    }
}

// ---------------- final: captions ----------------
__global__ void caption_kernel(float* __restrict__ cap_f, int* __restrict__ cap_i) {
    int idx = blockIdx.x * 256 + threadIdx.x;  // 2048
    int tt = idx & 63;
    int b = idx >> 6;
    int v = decode_tok(g_best[tt * BB + b]);
    if (cap_f) cap_f[b * TT + tt] = (float)v;
    if (cap_i) cap_i[b * TT + tt] = v;
}

// ---------------- final: transpose staging [b][t][v] -> out [b][v][t] -----
__global__ __launch_bounds__(256) void transpose_kernel(
    const float* __restrict__ stage, float* __restrict__ out) {
    __shared__ float tile[128][65];
    int b = blockIdx.x / 250;
    int vc = blockIdx.x % 250;
    int v0 = vc * 128;
    const float* src = stage + (size_t)b * TT * VV + v0;
#pragma unroll
    for (int l = 0; l < 32; l++) {
        int e = threadIdx.x + l * 256;
        int tt = e >> 7;
        int vi = e & 127;
        tile[vi][tt] = src[(size_t)tt * VV + vi];
    }
    __syncthreads();
    float* dst = out + ((size_t)b * VV + v0) * TT;
#pragma unroll
    for (int l = 0; l < 32; l++) {
        int e = threadIdx.x + l * 256;
        int vi = e >> 6;
        int tt = e & 63;
        dst[(size_t)vi * TT + tt] = tile[vi][tt];
    }
}

// ---------------- host threefry ----------------
static void host_threefry(unsigned k0, unsigned k1, unsigned x0, unsigned x1,
                          unsigned& o0, unsigned& o1) {
    unsigned ks2 = k0 ^ k1 ^ 0x1BD11BDAu;
    x0 += k0; x1 += k1;
#define HTF_RND(r) { x0 += x1; x1 = (x1 << r) | (x1 >> (32 - r)); x1 ^= x0; }
    HTF_RND(13) HTF_RND(15) HTF_RND(26) HTF_RND(6)  x0 += k1;  x1 += ks2 + 1u;
    HTF_RND(17) HTF_RND(29) HTF_RND(16) HTF_RND(24) x0 += ks2; x1 += k0 + 2u;
    HTF_RND(13) HTF_RND(15) HTF_RND(26) HTF_RND(6)  x0 += k0;  x1 += k1 + 3u;
    HTF_RND(17) HTF_RND(29) HTF_RND(16) HTF_RND(24) x0 += k1;  x1 += ks2 + 4u;
    HTF_RND(13) HTF_RND(15) HTF_RND(26) HTF_RND(6)  x0 += ks2; x1 += k0 + 5u;
#undef HTF_RND
    o0 = x0; o1 = x1;
}

extern "C" void kernel_launch(void* const* d_in, const int* in_sizes, int n_in,
                              void* d_out, int out_size) {
    const float* condition = (const float*)d_in[0];
    const float* Wh    = (const float*)d_in[1];
    const float* bh    = (const float*)d_in[2];
    const float* Wc    = (const float*)d_in[3];
    const float* bc    = (const float*)d_in[4];
    const float* embed = (const float*)d_in[5];
    const float* Wih   = (const float*)d_in[6];
    const float* bih   = (const float*)d_in[7];
    const float* Whh   = (const float*)d_in[8];
    const float* bhh   = (const float*)d_in[9];
    const float* Wout  = (const float*)d_in[10];
    const float* bout  = (const float*)d_in[11];

    float *hA, *hB, *cA, *cB, *xbuf, *stage;
    unsigned long long* best;
    cudaGetSymbolAddress((void**)&hA, g_hA);
    cudaGetSymbolAddress((void**)&hB, g_hB);
    cudaGetSymbolAddress((void**)&cA, g_cA);
    cudaGetSymbolAddress((void**)&cB, g_cB);
    cudaGetSymbolAddress((void**)&xbuf, g_x);
    cudaGetSymbolAddress((void**)&stage, g_stage);
    cudaGetSymbolAddress((void**)&best, g_best);

    const long long n_cap = (long long)BB * TT;
    const long long n_log = (long long)BB * VV * TT;
    float* cap_f = nullptr;
    int*   cap_i = nullptr;
    float* log_out = nullptr;
    long long osz = (long long)out_size;
    if (osz == n_cap + n_log) {
        cap_f = (float*)d_out;
        log_out = (float*)d_out + n_cap;
    } else if (osz == n_log) {
        log_out = (float*)d_out;
    } else if (osz == n_cap) {
        cap_i = (int*)d_out;
    } else {
        cap_f = (float*)d_out;
        log_out = (float*)d_out + n_cap;
    }

    init_kernel<<<128, 256>>>(condition, Wh, bh, Wc, bc, hA, cA);

    float *hcur = hA, *hnxt = hB, *ccur = cA, *cnxt = cB;
    for (int t = 0; t < TT; t++) {
        gather_kernel<<<64, 256>>>(embed, xbuf, t);
        lstm_kernel<<<512, 256>>>(xbuf, Wih, bih, Whh, bhh,
                                  hcur, ccur, hnxt, cnxt);
        unsigned o0, o1;
        host_threefry(0u, 42u, 0u, (unsigned)t, o0, o1);
        logits_kernel<<<250, 128>>>(hnxt, Wout, bout, stage, best, t, o0, o1);
        float* tmp;
        tmp = hcur; hcur = hnxt; hnxt = tmp;
        tmp = ccur; ccur = cnxt; cnxt = tmp;
    }
    caption_kernel<<<8, 256>>>(cap_f, cap_i);
    if (log_out) transpose_kernel<<<8000, 256>>>(stage, log_out);
}

// round 4
// speedup vs baseline: 2.9640x; 1.6791x over previous
#include <cuda_runtime.h>
#include <math.h>

#define BB 32
#define EE 512
#define HH 1024
#define VV 32000
#define TT 64
#define START_TOK 1
#define F32_TINY 1.17549435e-38f
#define KC 32
#define TILEV 128
#define NCHUNK_LOG (HH / KC)     // 16
#define KTOT 1536                // E + H unified K for lstm
#define SPLITK 4
#define KSEG (KTOT / SPLITK)     // 384
#define NCHUNK_LSTM (KSEG / KC)  // 12
#define WS_STRIDE 36

// ---------------- device scratch ----------------
__device__ __align__(16) float g_hA[HH * BB];   // [k][b]
__device__ __align__(16) float g_hB[HH * BB];
__device__ __align__(16) float g_cA[HH * BB];
__device__ __align__(16) float g_cB[HH * BB];
__device__ __align__(16) float g_xh[KTOT * BB]; // [k][b]: x (512) then h (1024)
__device__ __align__(16) float g_gpart[SPLITK * 4 * HH * BB]; // split-K partials
__device__ unsigned long long g_best[TT * BB];
__device__ __align__(16) float g_stage[(size_t)BB * TT * VV]; // [b][t][v]

// ---------------- f32x2 packed math ----------------
__device__ __forceinline__ unsigned long long pack2(float lo, float hi) {
    unsigned long long r;
    asm("mov.b64 %0, {%1, %2};" : "=l"(r) : "f"(lo), "f"(hi));
    return r;
}
__device__ __forceinline__ void unpack2(unsigned long long v, float& lo, float& hi) {
    asm("mov.b64 {%0, %1}, %2;" : "=f"(lo), "=f"(hi) : "l"(v));
}
__device__ __forceinline__ unsigned long long fma2(unsigned long long a,
                                                   unsigned long long b,
                                                   unsigned long long c) {
    unsigned long long d;
    asm("fma.rn.f32x2 %0, %1, %2, %3;" : "=l"(d) : "l"(a), "l"(b), "l"(c));
    return d;
}

// ---------------- threefry2x32 (JAX-compatible) ----------------
__device__ __forceinline__ void threefry2x32_dev(unsigned k0, unsigned k1,
                                                 unsigned x0, unsigned x1,
                                                 unsigned& o0, unsigned& o1) {
    unsigned ks2 = k0 ^ k1 ^ 0x1BD11BDAu;
    x0 += k0; x1 += k1;
#define TF_RND(r) { x0 += x1; x1 = __funnelshift_l(x1, x1, r); x1 ^= x0; }
    TF_RND(13) TF_RND(15) TF_RND(26) TF_RND(6)  x0 += k1;  x1 += ks2 + 1u;
    TF_RND(17) TF_RND(29) TF_RND(16) TF_RND(24) x0 += ks2; x1 += k0 + 2u;
    TF_RND(13) TF_RND(15) TF_RND(26) TF_RND(6)  x0 += k0;  x1 += k1 + 3u;
    TF_RND(17) TF_RND(29) TF_RND(16) TF_RND(24) x0 += k1;  x1 += ks2 + 4u;
    TF_RND(13) TF_RND(15) TF_RND(26) TF_RND(6)  x0 += ks2; x1 += k0 + 5u;
#undef TF_RND
    o0 = x0; o1 = x1;
}

__device__ __forceinline__ unsigned ford(float f) {
    unsigned u = __float_as_uint(f);
    return (u & 0x80000000u) ? ~u : (u | 0x80000000u);
}
__device__ __forceinline__ unsigned long long u64max(unsigned long long a,
                                                     unsigned long long b) {
    return a > b ? a : b;
}
__device__ __forceinline__ int decode_tok(unsigned long long key) {
    return (int)(0xFFFFFFFFu - (unsigned)(key & 0xFFFFFFFFull));
}

// ---------------- cp.async helpers ----------------
__device__ __forceinline__ void cp_async16(unsigned dst, const void* src) {
    asm volatile("cp.async.cg.shared.global [%0], [%1], 16;"
                 :: "r"(dst), "l"(src) : "memory");
}
__device__ __forceinline__ void cp_commit() {
    asm volatile("cp.async.commit_group;" ::: "memory");
}

// ---------------- K0: h0/c0 from condition; clear g_best ----------------
__global__ __launch_bounds__(256) void init_kernel(
    const float* __restrict__ cond, const float* __restrict__ Wh,
    const float* __restrict__ bh,   const float* __restrict__ Wc,
    const float* __restrict__ bc,
    float* __restrict__ hout, float* __restrict__ cout) {
    int j = blockIdx.x * 8 + (threadIdx.x >> 5);
    int lane = threadIdx.x & 31;
    if (blockIdx.x < 8) {
        int idx = blockIdx.x * 256 + threadIdx.x;
        if (idx < TT * BB) g_best[idx] = 0ull;
    }
    const float* cr = cond + (size_t)lane * EE;
    const float* wh = Wh + (size_t)j * EE;
    const float* wc = Wc + (size_t)j * EE;
    float ah = bh[j], ac = bc[j];
#pragma unroll 4
    for (int k = 0; k < EE; k += 4) {
        float4 c4 = *(const float4*)(cr + k);
        float4 h4 = *(const float4*)(wh + k);
        float4 q4 = *(const float4*)(wc + k);
        ah = fmaf(c4.x, h4.x, ah); ah = fmaf(c4.y, h4.y, ah);
        ah = fmaf(c4.z, h4.z, ah); ah = fmaf(c4.w, h4.w, ah);
        ac = fmaf(c4.x, q4.x, ac); ac = fmaf(c4.y, q4.y, ac);
        ac = fmaf(c4.z, q4.z, ac); ac = fmaf(c4.w, q4.w, ac);
    }
    hout[j * BB + lane] = ah;
    cout[j * BB + lane] = ac;
}

// ---------------- K-gather: build xh[k][b] = [embed(tok); h] ----------------
__global__ __launch_bounds__(256) void gather_kernel(
    const float* __restrict__ embed, const float* __restrict__ hin, int t) {
    int idx = blockIdx.x * 256 + threadIdx.x;  // 0..49151
    int b = idx & 31;
    int k = idx >> 5;
    float val;
    if (k < EE) {
        int tok = START_TOK;
        if (t > 0) tok = decode_tok(g_best[(t - 1) * BB + b]);
        val = embed[(size_t)tok * EE + k];
    } else {
        val = hin[(k - EE) * BB + b];
    }
    g_xh[k * BB + b] = val;
}

// ---------------- K1a: lstm gate GEMM (split-K) ----------------
// grid (32, 4): blockIdx.x = row tile (128 rows), blockIdx.y = K segment.
// 256 threads: rt=tid&31, bt=tid>>5; thread tile 4r x 4b.
__global__ __launch_bounds__(256) void lstm_gemm_kernel(
    const float* __restrict__ Wih, const float* __restrict__ Whh) {
    __shared__ __align__(16) float Ws[2][TILEV][WS_STRIDE];
    __shared__ __align__(16) float xs[2][KC][BB];
    int tid = threadIdx.x;
    int rt = tid & 31;
    int bt = tid >> 5;
    int m0 = blockIdx.x * TILEV;
    int seg = blockIdx.y;
    int k0seg = seg * KSEG;

    int srow = tid >> 1;
    int sko = (tid & 1) * 16;
    unsigned wdst0 = (unsigned)__cvta_generic_to_shared(&Ws[0][srow][sko]);
    unsigned wdst1 = (unsigned)__cvta_generic_to_shared(&Ws[1][srow][sko]);
    unsigned xdst0 = (unsigned)__cvta_generic_to_shared(&xs[0][0][0]) + tid * 16;
    unsigned xdst1 = (unsigned)__cvta_generic_to_shared(&xs[1][0][0]) + tid * 16;

    auto do_stage = [&](int buf, int c) {
        int kk = k0seg + c * KC;
        const float* wsrc;
        if (kk < EE) wsrc = Wih + (size_t)(m0 + srow) * EE + kk + sko;
        else         wsrc = Whh + (size_t)(m0 + srow) * HH + (kk - EE) + sko;
        unsigned wd = buf ? wdst1 : wdst0;
#pragma unroll
        for (int ch = 0; ch < 4; ch++)
            cp_async16(wd + ch * 16, wsrc + ch * 4);
        cp_async16(buf ? xdst1 : xdst0, g_xh + (size_t)kk * BB + tid * 4);
        cp_commit();
    };

    do_stage(0, 0);
    do_stage(1, 1);

    unsigned long long acc[4][2];
#pragma unroll
    for (int rj = 0; rj < 4; rj++) { acc[rj][0] = 0ull; acc[rj][1] = 0ull; }

    for (int c = 0; c < NCHUNK_LSTM; c++) {
        if (c == NCHUNK_LSTM - 1)
            asm volatile("cp.async.wait_group 0;" ::: "memory");
        else
            asm volatile("cp.async.wait_group 1;" ::: "memory");
        __syncthreads();
        int buf = c & 1;
#pragma unroll
        for (int k4 = 0; k4 < KC / 4; k4++) {
            unsigned long long h01[4], h23[4];
#pragma unroll
            for (int i = 0; i < 4; i++) {
                float4 h4 = *(const float4*)&xs[buf][k4 * 4 + i][bt * 4];
                h01[i] = pack2(h4.x, h4.y);
                h23[i] = pack2(h4.z, h4.w);
            }
#pragma unroll
            for (int rj = 0; rj < 4; rj++) {
                float4 w4 = *(const float4*)&Ws[buf][rt + 32 * rj][k4 * 4];
                unsigned long long w;
                w = pack2(w4.x, w4.x);
                acc[rj][0] = fma2(w, h01[0], acc[rj][0]);
                acc[rj][1] = fma2(w, h23[0], acc[rj][1]);
                w = pack2(w4.y, w4.y);
                acc[rj][0] = fma2(w, h01[1], acc[rj][0]);
                acc[rj][1] = fma2(w, h23[1], acc[rj][1]);
                w = pack2(w4.z, w4.z);
                acc[rj][0] = fma2(w, h01[2], acc[rj][0]);
                acc[rj][1] = fma2(w, h23[2], acc[rj][1]);
                w = pack2(w4.w, w4.w);
                acc[rj][0] = fma2(w, h01[3], acc[rj][0]);
                acc[rj][1] = fma2(w, h23[3], acc[rj][1]);
            }
        }
        __syncthreads();
        if (c + 2 < NCHUNK_LSTM) do_stage(buf, c + 2);
    }

    float* part = g_gpart + (size_t)seg * 4 * HH * BB;
#pragma unroll
    for (int rj = 0; rj < 4; rj++) {
        int r = m0 + rt + 32 * rj;
        float p[4];
        unpack2(acc[rj][0], p[0], p[1]);
        unpack2(acc[rj][1], p[2], p[3]);
#pragma unroll
        for (int bi = 0; bi < 4; bi++)
            part[(size_t)r * BB + bt * 4 + bi] = p[bi];
    }
}

// ---------------- K1b: combine partials + cell ----------------
__global__ __launch_bounds__(256) void cell_kernel(
    const float* __restrict__ bih, const float* __restrict__ bhh,
    const float* __restrict__ cin,
    float* __restrict__ hout, float* __restrict__ cout) {
    int idx = blockIdx.x * 256 + threadIdx.x;  // 0..32767
    int b = idx & 31;
    int j = idx >> 5;
    float a[4] = {0.f, 0.f, 0.f, 0.f};
#pragma unroll
    for (int seg = 0; seg < SPLITK; seg++) {
        const float* part = g_gpart + (size_t)seg * 4 * HH * BB;
#pragma unroll
        for (int gate = 0; gate < 4; gate++)
            a[gate] += part[(size_t)(gate * HH + j) * BB + b];
    }
#pragma unroll
    for (int gate = 0; gate < 4; gate++) {
        int r = gate * HH + j;
        a[gate] += bih[r] + bhh[r];
    }
    float ig = 1.0f / (1.0f + expf(-a[0]));
    float fg = 1.0f / (1.0f + expf(-a[1]));
    float gg = tanhf(a[2]);
    float og = 1.0f / (1.0f + expf(-a[3]));
    float c = fg * cin[j * BB + b] + ig * gg;
    float h = og * tanhf(c);
    cout[j * BB + b] = c;
    hout[j * BB + b] = h;
}

// ---------------- K2: logits GEMM + gumbel + atomic argmax ----------------
// 256 threads: vt=tid&31, bt=tid>>5; thread tile 4v x 4b; TILEV=128.
__global__ __launch_bounds__(256) void logits_kernel(
    const float* __restrict__ hT, const float* __restrict__ Wout,
    const float* __restrict__ bout, float* __restrict__ stage,
    unsigned long long* __restrict__ best, int t, unsigned key0, unsigned key1) {
    __shared__ __align__(16) float Ws[2][TILEV][WS_STRIDE];
    __shared__ __align__(16) float hs[2][KC][BB];
    int tid = threadIdx.x;
    int vt = tid & 31;
    int bt = tid >> 5;
    int v0 = blockIdx.x * TILEV;

    int srow = tid >> 1;
    int sko = (tid & 1) * 16;
    unsigned wdst0 = (unsigned)__cvta_generic_to_shared(&Ws[0][srow][sko]);
    unsigned wdst1 = (unsigned)__cvta_generic_to_shared(&Ws[1][srow][sko]);
    unsigned hdst0 = (unsigned)__cvta_generic_to_shared(&hs[0][0][0]) + tid * 16;
    unsigned hdst1 = (unsigned)__cvta_generic_to_shared(&hs[1][0][0]) + tid * 16;

    auto do_stage = [&](int buf, int c) {
        int kc = c * KC;
        const float* wsrc = Wout + (size_t)(v0 + srow) * HH + kc + sko;
        unsigned wd = buf ? wdst1 : wdst0;
#pragma unroll
        for (int ch = 0; ch < 4; ch++)
            cp_async16(wd + ch * 16, wsrc + ch * 4);
        cp_async16(buf ? hdst1 : hdst0, hT + (size_t)kc * BB + tid * 4);
        cp_commit();
    };

    do_stage(0, 0);
    do_stage(1, 1);

    unsigned long long acc[4][2];
#pragma unroll
    for (int vj = 0; vj < 4; vj++) { acc[vj][0] = 0ull; acc[vj][1] = 0ull; }

    for (int c = 0; c < NCHUNK_LOG; c++) {
        if (c == NCHUNK_LOG - 1)
            asm volatile("cp.async.wait_group 0;" ::: "memory");
        else
            asm volatile("cp.async.wait_group 1;" ::: "memory");
        __syncthreads();
        int buf = c & 1;
#pragma unroll
        for (int k4 = 0; k4 < KC / 4; k4++) {
            unsigned long long h01[4], h23[4];
#pragma unroll
            for (int i = 0; i < 4; i++) {
                float4 h4 = *(const float4*)&hs[buf][k4 * 4 + i][bt * 4];
                h01[i] = pack2(h4.x, h4.y);
                h23[i] = pack2(h4.z, h4.w);
            }
#pragma unroll
            for (int vj = 0; vj < 4; vj++) {
                float4 w4 = *(const float4*)&Ws[buf][vt + 32 * vj][k4 * 4];
                unsigned long long w;
                w = pack2(w4.x, w4.x);
                acc[vj][0] = fma2(w, h01[0], acc[vj][0]);
                acc[vj][1] = fma2(w, h23[0], acc[vj][1]);
                w = pack2(w4.y, w4.y);
                acc[vj][0] = fma2(w, h01[1], acc[vj][0]);
                acc[vj][1] = fma2(w, h23[1], acc[vj][1]);
                w = pack2(w4.z, w4.z);
                acc[vj][0] = fma2(w, h01[2], acc[vj][0]);
                acc[vj][1] = fma2(w, h23[2], acc[vj][1]);
                w = pack2(w4.w, w4.w);
                acc[vj][0] = fma2(w, h01[3], acc[vj][0]);
                acc[vj][1] = fma2(w, h23[3], acc[vj][1]);
            }
        }
        __syncthreads();
        if (c + 2 < NCHUNK_LOG) do_stage(buf, c + 2);
    }

    // epilogue: bias, store to staging [b][t][v], gumbel, argmax
    float lg[4][4];
#pragma unroll
    for (int vj = 0; vj < 4; vj++) {
        unpack2(acc[vj][0], lg[vj][0], lg[vj][1]);
        unpack2(acc[vj][1], lg[vj][2], lg[vj][3]);
        float bo = bout[v0 + vt + 32 * vj];
#pragma unroll
        for (int bi = 0; bi < 4; bi++) lg[vj][bi] += bo;
    }
#pragma unroll
    for (int bi = 0; bi < 4; bi++) {
        int b = bt * 4 + bi;
        float* sp = stage + ((size_t)b * TT + t) * VV + v0 + vt;
        unsigned long long bk = 0ull;
#pragma unroll
        for (int vj = 0; vj < 4; vj++) {
            int v = v0 + vt + 32 * vj;
            float logit = lg[vj][bi];
            sp[32 * vj] = logit;
            unsigned i = (unsigned)(b * VV + v);
            unsigned o0, o1;
            threefry2x32_dev(key0, key1, 0u, i, o0, o1);
            unsigned bits = o0 ^ o1;
            float u = __uint_as_float(0x3f800000u | (bits >> 9)) - 1.0f;
            u = fmaxf(u + F32_TINY, F32_TINY);
            float g = -logf(-logf(u));
            float val = logit + g;
            unsigned long long key =
                ((unsigned long long)ford(val) << 32) |
                (unsigned long long)(0xFFFFFFFFu - (unsigned)v);
            bk = u64max(bk, key);
        }
#pragma unroll
        for (int off = 1; off < 32; off <<= 1) {
            unsigned long long o = __shfl_xor_sync(0xffffffffu, bk, off);
            bk = u64max(bk, o);
        }
        if (vt == 0) atomicMax(&best[t * BB + b], bk);
    }
}

// ---------------- final: captions ----------------
__global__ void caption_kernel(float* __restrict__ cap_f, int* __restrict__ cap_i) {
    int idx = blockIdx.x * 256 + threadIdx.x;  // 2048
    int tt = idx & 63;
    int b = idx >> 6;
    int v = decode_tok(g_best[tt * BB + b]);
    if (cap_f) cap_f[b * TT + tt] = (float)v;
    if (cap_i) cap_i[b * TT + tt] = v;
}

// ---------------- final: transpose staging [b][t][v] -> out [b][v][t] -----
__global__ __launch_bounds__(256) void transpose_kernel(
    const float* __restrict__ stage, float* __restrict__ out) {
    __shared__ float tile[128][65];
    int b = blockIdx.x / 250;
    int vc = blockIdx.x % 250;
    int v0 = vc * 128;
    const float* src = stage + (size_t)b * TT * VV + v0;
#pragma unroll
    for (int l = 0; l < 32; l++) {
        int e = threadIdx.x + l * 256;
        int tt = e >> 7;
        int vi = e & 127;
        tile[vi][tt] = src[(size_t)tt * VV + vi];
    }
    __syncthreads();
    float* dst = out + ((size_t)b * VV + v0) * TT;
#pragma unroll
    for (int l = 0; l < 32; l++) {
        int e = threadIdx.x + l * 256;
        int vi = e >> 6;
        int tt = e & 63;
        dst[(size_t)vi * TT + tt] = tile[vi][tt];
    }
}

// ---------------- host threefry ----------------
static void host_threefry(unsigned k0, unsigned k1, unsigned x0, unsigned x1,
                          unsigned& o0, unsigned& o1) {
    unsigned ks2 = k0 ^ k1 ^ 0x1BD11BDAu;
    x0 += k0; x1 += k1;
#define HTF_RND(r) { x0 += x1; x1 = (x1 << r) | (x1 >> (32 - r)); x1 ^= x0; }
    HTF_RND(13) HTF_RND(15) HTF_RND(26) HTF_RND(6)  x0 += k1;  x1 += ks2 + 1u;
    HTF_RND(17) HTF_RND(29) HTF_RND(16) HTF_RND(24) x0 += ks2; x1 += k0 + 2u;
    HTF_RND(13) HTF_RND(15) HTF_RND(26) HTF_RND(6)  x0 += k0;  x1 += k1 + 3u;
    HTF_RND(17) HTF_RND(29) HTF_RND(16) HTF_RND(24) x0 += k1;  x1 += ks2 + 4u;
    HTF_RND(13) HTF_RND(15) HTF_RND(26) HTF_RND(6)  x0 += ks2; x1 += k0 + 5u;
#undef HTF_RND
    o0 = x0; o1 = x1;
}

extern "C" void kernel_launch(void* const* d_in, const int* in_sizes, int n_in,
                              void* d_out, int out_size) {
    const float* condition = (const float*)d_in[0];
    const float* Wh    = (const float*)d_in[1];
    const float* bh    = (const float*)d_in[2];
    const float* Wc    = (const float*)d_in[3];
    const float* bc    = (const float*)d_in[4];
    const float* embed = (const float*)d_in[5];
    const float* Wih   = (const float*)d_in[6];
    const float* bih   = (const float*)d_in[7];
    const float* Whh   = (const float*)d_in[8];
    const float* bhh   = (const float*)d_in[9];
    const float* Wout  = (const float*)d_in[10];
    const float* bout  = (const float*)d_in[11];

    float *hA, *hB, *cA, *cB, *stage;
    unsigned long long* best;
    cudaGetSymbolAddress((void**)&hA, g_hA);
    cudaGetSymbolAddress((void**)&hB, g_hB);
    cudaGetSymbolAddress((void**)&cA, g_cA);
    cudaGetSymbolAddress((void**)&cB, g_cB);
    cudaGetSymbolAddress((void**)&stage, g_stage);
    cudaGetSymbolAddress((void**)&best, g_best);

    const long long n_cap = (long long)BB * TT;
    const long long n_log = (long long)BB * VV * TT;
    float* cap_f = nullptr;
    int*   cap_i = nullptr;
    float* log_out = nullptr;
    long long osz = (long long)out_size;
    if (osz == n_cap + n_log) {
        cap_f = (float*)d_out;
        log_out = (float*)d_out + n_cap;
    } else if (osz == n_log) {
        log_out = (float*)d_out;
    } else if (osz == n_cap) {
        cap_i = (int*)d_out;
    } else {
        cap_f = (float*)d_out;
        log_out = (float*)d_out + n_cap;
    }

    init_kernel<<<128, 256>>>(condition, Wh, bh, Wc, bc, hA, cA);

    float *hcur = hA, *hnxt = hB, *ccur = cA, *cnxt = cB;
    for (int t = 0; t < TT; t++) {
        gather_kernel<<<192, 256>>>(embed, hcur, t);
        dim3 ggrid(HH * 4 / TILEV, SPLITK);
        lstm_gemm_kernel<<<ggrid, 256>>>(Wih, Whh);
        cell_kernel<<<128, 256>>>(bih, bhh, ccur, hnxt, cnxt);
        unsigned o0, o1;
        host_threefry(0u, 42u, 0u, (unsigned)t, o0, o1);
        logits_kernel<<<250, 256>>>(hnxt, Wout, bout, stage, best, t, o0, o1);
        float* tmp;
        tmp = hcur; hcur = hnxt; hnxt = tmp;
        tmp = ccur; ccur = cnxt; cnxt = tmp;
    }
    caption_kernel<<<8, 256>>>(cap_f, cap_i);
    if (log_out) transpose_kernel<<<8000, 256>>>(stage, log_out);
}